// round 11
// baseline (speedup 1.0000x reference)
#include <cuda_runtime.h>

#define BB 8
#define NN 4096
#define DD 1024
#define NB 512          // all resident: 512 <= 4 * 148 SMs
#define KS 16           // k-slices in column-GEMV
#define DT 4            // d-tiles in column-GEMV

// ---------------- device scratch (no allocations allowed) ----------------
__device__ __align__(16) float g_Wgm[DD * DD];
__device__ __align__(16) float g_b[BB * NN];
__device__ __align__(16) float g_c[BB * NN];
__device__ __align__(16) float g_delta[BB * NN];
__device__ __align__(16) float g_qA[BB * DD];    // holds q0, later q2
__device__ __align__(16) float g_qB[BB * DD];    // holds q1
__device__ __align__(16) float g_tmp[BB * DD];
__device__ __align__(16) float g_tmp2[BB * DD];
__device__ __align__(16) float g_qt[BB * DD];
__device__ __align__(16) float g_outv[BB * DD];
__device__ __align__(16) float g_part[BB * 64 * DD];
__device__ __align__(16) float g_cpart[KS * BB * DD];
__device__ unsigned g_cnt[DT];        // zero-init, self-resetting
__device__ unsigned g_bar_count;      // zero-init, self-resetting
__device__ unsigned g_bar_sense;      // read at kernel start (any parity ok)

// ---------------- helpers ----------------
__device__ __forceinline__ float warpSum(float v) {
    #pragma unroll
    for (int o = 16; o; o >>= 1) v += __shfl_xor_sync(0xffffffffu, v, o);
    return v;
}
__device__ __forceinline__ float warpMax(float v) {
    #pragma unroll
    for (int o = 16; o; o >>= 1) v = fmaxf(v, __shfl_xor_sync(0xffffffffu, v, o));
    return v;
}
__device__ __forceinline__ float selu_f(float x) {
    const float A = 1.6732632423543772f, S = 1.0507009873554805f;
    return (x > 0.f) ? S * x : S * A * expm1f(x);
}

// grid-wide sense-reversing barrier; all NB blocks call it equally often.
__device__ __forceinline__ void gbar(unsigned& sense) {
    __threadfence();
    __syncthreads();
    sense ^= 1u;
    if (threadIdx.x == 0) {
        unsigned a = atomicAdd(&g_bar_count, 1u);
        if (a == NB - 1) {
            g_bar_count = 0;
            __threadfence();
            atomicExch(&g_bar_sense, sense);
        } else {
            while (*(volatile unsigned*)&g_bar_sense != sense) __nanosleep(32);
        }
    }
    __syncthreads();
    __threadfence();
}

// softmax over 4096 values held 16/thread in v[]; writes g_c[b]. 256 threads.
__device__ void softmax_store(int b, float* v) {
    __shared__ float red[8];
    int t = threadIdx.x;
    float mx = -3.0e38f;
    #pragma unroll
    for (int i = 0; i < 16; i++) mx = fmaxf(mx, v[i]);
    mx = warpMax(mx);
    if ((t & 31) == 0) red[t >> 5] = mx;
    __syncthreads();
    mx = red[0];
    #pragma unroll
    for (int w = 1; w < 8; w++) mx = fmaxf(mx, red[w]);
    float sum = 0.f;
    #pragma unroll
    for (int i = 0; i < 16; i++) { v[i] = expf(v[i] - mx); sum += v[i]; }
    sum = warpSum(sum);
    __syncthreads();
    if ((t & 31) == 0) red[t >> 5] = sum;
    __syncthreads();
    sum = 0.f;
    #pragma unroll
    for (int w = 0; w < 8; w++) sum += red[w];
    float inv = 1.0f / sum;
    #pragma unroll
    for (int i = 0; i < 16; i++) g_c[b * NN + i * 256 + t] = v[i] * inv;
}

// per-warp LN stats for batch b over v(d) = qold[d] + selu(outv[d]*invn)
__device__ __forceinline__ void q_stats(const float* __restrict__ qold,
                                        const float* __restrict__ outv,
                                        int b, float invn, int lane,
                                        float& mu, float& rstd) {
    float s1 = 0.f, s2 = 0.f;
    #pragma unroll 8
    for (int k = 0; k < 32; k++) {
        int d = k * 32 + lane;
        float v = qold[b * DD + d] + selu_f(outv[b * DD + d] * invn);
        s1 += v; s2 += v * v;
    }
    s1 = warpSum(s1); s2 = warpSum(s2);
    mu = s1 / (float)DD;
    float var = fmaxf(s2 / (float)DD - mu * mu, 0.f);
    rstd = rsqrtf(var + 1e-5f);
}

// shared compute tail of the split-K column-GEMV. sx[b][64] in smem.
__device__ void colmv_compute(const float* __restrict__ M,
                              const float sx[BB][64], float* __restrict__ Y,
                              int dt, int ks) {
    __shared__ unsigned done;
    int d = dt * 256 + threadIdx.x;
    float acc[BB];
    #pragma unroll
    for (int b = 0; b < BB; b++) acc[b] = 0.f;
    const float* Mp = M + (size_t)(ks * 64) * DD + d;
    #pragma unroll 8
    for (int k = 0; k < 64; k++) {
        float m = Mp[(size_t)k * DD];
        #pragma unroll
        for (int b = 0; b < BB; b++) acc[b] += sx[b][k] * m;
    }
    #pragma unroll
    for (int b = 0; b < BB; b++) g_cpart[(ks * BB + b) * DD + d] = acc[b];
    __threadfence();
    __syncthreads();
    if (threadIdx.x == 0) done = atomicAdd(&g_cnt[dt], 1u);
    __syncthreads();
    if (done == KS - 1) {
        #pragma unroll
        for (int b = 0; b < BB; b++) {
            float s = 0.f;
            #pragma unroll
            for (int k2 = 0; k2 < KS; k2++)
                s += __ldcg(&g_cpart[(k2 * BB + b) * DD + d]);
            Y[b * DD + d] = s;
        }
        __syncthreads();
        if (threadIdx.x == 0) g_cnt[dt] = 0;
    }
}

// plain column-GEMV: X read from global
__device__ void colmv_plain(const float* __restrict__ M, const float* __restrict__ X,
                            float* __restrict__ Y, int cb) {
    __shared__ float sx[BB][64];
    int dt = cb & (DT - 1), ks = cb >> 2;
    for (int i = threadIdx.x; i < BB * 64; i += 256)
        sx[i >> 6][i & 63] = X[(i >> 6) * DD + ks * 64 + (i & 63)];
    __syncthreads();
    colmv_compute(M, sx, Y, dt, ks);
}

// column-GEMV with inline q-update: X = LN(qold + selu(outv*invn)).
__device__ void colmv_q(const float* __restrict__ M,
                        const float* __restrict__ qold,
                        const float* __restrict__ outv,
                        const float* __restrict__ lnw,
                        const float* __restrict__ lnb,
                        float invn, int write_q, float* __restrict__ qdst,
                        float* __restrict__ Y, int cb) {
    __shared__ float sx[BB][64];
    int warp = threadIdx.x >> 5, lane = threadIdx.x & 31;
    int dt = cb & (DT - 1), ks = cb >> 2;
    float mu, rstd;
    q_stats(qold, outv, warp, invn, lane, mu, rstd);
    #pragma unroll
    for (int j = 0; j < 2; j++) {
        int d = ks * 64 + j * 32 + lane;
        float v = qold[warp * DD + d] + selu_f(outv[warp * DD + d] * invn);
        sx[warp][j * 32 + lane] = (v - mu) * rstd * lnw[d] + lnb[d];
    }
    if (write_q) {
        #pragma unroll 4
        for (int k = 0; k < 32; k++) {
            int d = k * 32 + lane;
            float v = qold[warp * DD + d] + selu_f(outv[warp * DD + d] * invn);
            qdst[warp * DD + d] = (v - mu) * rstd * lnw[d] + lnb[d];
        }
    }
    __syncthreads();
    colmv_compute(M, sx, Y, dt, ks);
}

// column-GEMV fused with s-reduction: X[b,k] = sum over 64 chunks of g_part.
__device__ void colmv_s(const float* __restrict__ M, float* __restrict__ Y, int cb) {
    __shared__ float sx[BB][64];
    int dt = cb & (DT - 1), ks = cb >> 2;
    #pragma unroll
    for (int p = 0; p < 2; p++) {
        int idx = p * 256 + threadIdx.x;
        int b = idx >> 6, kk = idx & 63;
        const float* pp = g_part + (size_t)(b * 64) * DD + ks * 64 + kk;
        float a0 = 0.f, a1 = 0.f, a2 = 0.f, a3 = 0.f;
        #pragma unroll 4
        for (int c = 0; c < 64; c += 4) {
            a0 += pp[(size_t)c * DD];
            a1 += pp[(size_t)(c + 1) * DD];
            a2 += pp[(size_t)(c + 2) * DD];
            a3 += pp[(size_t)(c + 3) * DD];
        }
        sx[b][kk] = (a0 + a1) + (a2 + a3);
    }
    __syncthreads();
    colmv_compute(M, sx, Y, dt, ks);
}

// row-dot matvec over all NB blocks: Y[b,r] = dot(M[r,:], X[b,:]) (+bias).
__device__ void rowdot(const float* __restrict__ M, const float* __restrict__ X,
                       float* __restrict__ Y, const float* __restrict__ bias,
                       char* smraw) {
    float4* shX = (float4*)smraw;                  // 2048 f4 = 32 KB
    const float4* Xv = (const float4*)X;
    #pragma unroll
    for (int i = threadIdx.x; i < BB * DD / 4; i += 256) shX[i] = Xv[i];
    __syncthreads();
    int warp = threadIdx.x >> 5, lane = threadIdx.x & 31;
    int row = blockIdx.x * 2 + (warp & 1);
    int b0 = (warp >> 1) * 2;
    const float4* Mr = (const float4*)(M + (size_t)row * DD);
    float a0 = 0.f, a1 = 0.f;
    #pragma unroll
    for (int j = 0; j < 8; j++) {
        float4 m = Mr[j * 32 + lane];
        float4 x0 = shX[b0 * 256 + j * 32 + lane];
        float4 x1 = shX[(b0 + 1) * 256 + j * 32 + lane];
        a0 += m.x * x0.x + m.y * x0.y + m.z * x0.z + m.w * x0.w;
        a1 += m.x * x1.x + m.y * x1.y + m.z * x1.z + m.w * x1.w;
    }
    a0 = warpSum(a0); a1 = warpSum(a1);
    if (lane == 0) {
        float bo = bias ? bias[row] : 0.f;
        Y[(size_t)b0 * DD + row] = a0 + bo;
        Y[(size_t)(b0 + 1) * DD + row] = a1 + bo;
    }
    __syncthreads();
}

// final row-dot with inline q-update: X = LN(qold + selu(outv)).
__device__ void rowdot_q(const float* __restrict__ M,
                         const float* __restrict__ qold,
                         const float* __restrict__ outv,
                         const float* __restrict__ lnw,
                         const float* __restrict__ lnb,
                         float* __restrict__ Y, const float* __restrict__ bias,
                         char* smraw) {
    float* shX = (float*)smraw;                    // [8][1024] = 32 KB
    int warp = threadIdx.x >> 5, lane = threadIdx.x & 31;
    float mu, rstd;
    q_stats(qold, outv, warp, 1.0f, lane, mu, rstd);
    #pragma unroll 4
    for (int k = 0; k < 32; k++) {
        int d = k * 32 + lane;
        float v = qold[warp * DD + d] + selu_f(outv[warp * DD + d]);
        shX[warp * DD + d] = (v - mu) * rstd * lnw[d] + lnb[d];
    }
    __syncthreads();
    int row = blockIdx.x * 2 + (warp & 1);
    int b0 = (warp >> 1) * 2;
    const float4* Mr = (const float4*)(M + (size_t)row * DD);
    const float4* x0p = (const float4*)(shX + b0 * DD);
    const float4* x1p = (const float4*)(shX + (b0 + 1) * DD);
    float a0 = 0.f, a1 = 0.f;
    #pragma unroll
    for (int j = 0; j < 8; j++) {
        float4 m = Mr[j * 32 + lane];
        float4 x0 = x0p[j * 32 + lane];
        float4 x1 = x1p[j * 32 + lane];
        a0 += m.x * x0.x + m.y * x0.y + m.z * x0.z + m.w * x0.w;
        a1 += m.x * x1.x + m.y * x1.y + m.z * x1.z + m.w * x1.w;
    }
    a0 = warpSum(a0); a1 = warpSum(a1);
    if (lane == 0) {
        float bo = bias[row];
        Y[(size_t)b0 * DD + row] = a0 + bo;
        Y[(size_t)(b0 + 1) * DD + row] = a1 + bo;
    }
}

// ---------------- big streaming pass with cp.async double buffering --------
// 512 blocks = (batch b = bid>>6, chunk = bid&63). 64 rows per block,
// 16 stages x 4 rows (16 KB contiguous), 2 smem buffers.
// Warp w: row (w>>1) of the stage, half (w&1) of the row.
#define PASS_PREFETCH(st) do {                                            \
    unsigned dstb = smbuf_u32 + (((st) & 1) ? 16384u : 0u);               \
    const float4* srcp = fb + (size_t)(st) * 1024;                        \
    _Pragma("unroll")                                                     \
    for (int j = 0; j < 4; j++) {                                         \
        unsigned da = dstb + (threadIdx.x + j * 256) * 16u;               \
        asm volatile("cp.async.cg.shared.global [%0], [%1], 16;"          \
                     :: "r"(da), "l"(srcp + threadIdx.x + j * 256));      \
    }                                                                     \
    asm volatile("cp.async.commit_group;");                               \
} while (0)

__device__ void pass_phase(const float* __restrict__ feat, int want_delta,
                           char* smraw) {
    float4* buf   = (float4*)smraw;               // [2][1024] f4 = 32 KB
    float4* sh_s  = (float4*)(smraw + 32768);     // 256 f4 = 4 KB
    float*  sh_c  = (float*)(smraw + 36864);      // 64 floats
    float*  sh_dp = (float*)(smraw + 37120);      // 16*8 floats
    unsigned smbuf_u32 = (unsigned)__cvta_generic_to_shared(buf);

    int b = blockIdx.x >> 6, chunk = blockIdx.x & 63;
    int warp = threadIdx.x >> 5, lane = threadIdx.x & 31;
    int row = warp >> 1, half = warp & 1;
    int cbase = half * 128 + lane;                // column float4 index base
    int rbase = row * 256 + cbase;                // within-stage float4 index

    if (threadIdx.x < 64) sh_c[threadIdx.x] = g_c[b * NN + chunk * 64 + threadIdx.x];
    const float4* qtv = (const float4*)(g_qt + b * DD);
    float4 q0 = qtv[cbase], q1 = qtv[cbase + 32],
           q2 = qtv[cbase + 64], q3 = qtv[cbase + 96];
    float4 s0 = make_float4(0.f, 0.f, 0.f, 0.f), s1 = s0, s2 = s0, s3 = s0;

    const float4* fb = (const float4*)feat + ((size_t)b * NN + chunk * 64) * 256;

    PASS_PREFETCH(0);
    PASS_PREFETCH(1);

    for (int s = 0; s < 16; s++) {
        if (s < 15) asm volatile("cp.async.wait_group 1;");
        else        asm volatile("cp.async.wait_group 0;");
        __syncthreads();                      // stage s ready; prev compute done
        const float4* rp = buf + ((s & 1) ? 1024 : 0) + rbase;
        float4 v0 = rp[0], v1 = rp[32], v2 = rp[64], v3 = rp[96];
        float cw = sh_c[s * 4 + row];
        if (want_delta) {
            float dp = v0.x*q0.x + v0.y*q0.y + v0.z*q0.z + v0.w*q0.w
                     + v1.x*q1.x + v1.y*q1.y + v1.z*q1.z + v1.w*q1.w
                     + v2.x*q2.x + v2.y*q2.y + v2.z*q2.z + v2.w*q2.w
                     + v3.x*q3.x + v3.y*q3.y + v3.z*q3.z + v3.w*q3.w;
            dp = warpSum(dp);
            if (lane == 0) sh_dp[s * 8 + row * 2 + half] = dp;
        }
        s0.x += cw*v0.x; s0.y += cw*v0.y; s0.z += cw*v0.z; s0.w += cw*v0.w;
        s1.x += cw*v1.x; s1.y += cw*v1.y; s1.z += cw*v1.z; s1.w += cw*v1.w;
        s2.x += cw*v2.x; s2.y += cw*v2.y; s2.z += cw*v2.z; s2.w += cw*v2.w;
        s3.x += cw*v3.x; s3.y += cw*v3.y; s3.z += cw*v3.z; s3.w += cw*v3.w;
        __syncthreads();                      // all done reading buf[s&1]
        if (s + 2 < 16) PASS_PREFETCH(s + 2);
    }

    if (want_delta && threadIdx.x < 64) {
        int st = threadIdx.x >> 2, r = threadIdx.x & 3;
        g_delta[b * NN + chunk * 64 + threadIdx.x] =
            sh_dp[st * 8 + r * 2] + sh_dp[st * 8 + r * 2 + 1];
    }
    // staggered deterministic s-reduce: 4 warps per half (rows 0..3)
    #pragma unroll
    for (int w = 0; w < 4; w++) {
        if (row == w) {
            if (w == 0) {
                sh_s[cbase] = s0; sh_s[cbase + 32] = s1;
                sh_s[cbase + 64] = s2; sh_s[cbase + 96] = s3;
            } else {
                float4 t;
                t = sh_s[cbase];      t.x+=s0.x; t.y+=s0.y; t.z+=s0.z; t.w+=s0.w; sh_s[cbase]      = t;
                t = sh_s[cbase + 32]; t.x+=s1.x; t.y+=s1.y; t.z+=s1.z; t.w+=s1.w; sh_s[cbase + 32] = t;
                t = sh_s[cbase + 64]; t.x+=s2.x; t.y+=s2.y; t.z+=s2.z; t.w+=s2.w; sh_s[cbase + 64] = t;
                t = sh_s[cbase + 96]; t.x+=s3.x; t.y+=s3.y; t.z+=s3.z; t.w+=s3.w; sh_s[cbase + 96] = t;
            }
        }
        __syncthreads();
    }
    float4* pp = (float4*)(g_part + ((size_t)b * 64 + chunk) * DD);
    pp[threadIdx.x] = sh_s[threadIdx.x];
    __syncthreads();
}

// b += standardize(delta, ddof=1), then c = softmax(b). One block per batch.
__device__ void bupd(int b) {
    __shared__ float red2[16];
    int t = threadIdx.x;
    float v[16];
    float s1 = 0.f, s2 = 0.f;
    #pragma unroll
    for (int i = 0; i < 16; i++) {
        v[i] = g_delta[b * NN + i * 256 + t];
        s1 += v[i]; s2 += v[i] * v[i];
    }
    s1 = warpSum(s1); s2 = warpSum(s2);
    if ((t & 31) == 0) { red2[t >> 5] = s1; red2[8 + (t >> 5)] = s2; }
    __syncthreads();
    s1 = 0.f; s2 = 0.f;
    #pragma unroll
    for (int w = 0; w < 8; w++) { s1 += red2[w]; s2 += red2[8 + w]; }
    float mean = s1 / (float)NN;
    float var = fmaxf((s2 - s1 * s1 / (float)NN) / (float)(NN - 1), 0.f);
    float inv = 1.0f / (sqrtf(var) + 1e-9f);
    #pragma unroll
    for (int i = 0; i < 16; i++) {
        float nb = g_b[b * NN + i * 256 + t] + (v[i] - mean) * inv;
        g_b[b * NN + i * 256 + t] = nb;
        v[i] = nb;
    }
    __syncthreads();
    softmax_store(b, v);
}

// standalone q-update for one batch: qdst = LN(qold+selu(outv*invn))
__device__ void qupd_block(int b, const float* __restrict__ qold,
                           const float* __restrict__ outv,
                           const float* __restrict__ lnw,
                           const float* __restrict__ lnb,
                           float invn, float* __restrict__ qdst) {
    __shared__ float red[16];
    int t = threadIdx.x;
    float v[4];
    float s1 = 0.f, s2 = 0.f;
    #pragma unroll
    for (int i = 0; i < 4; i++) {
        int d = i * 256 + t;
        v[i] = qold[b * DD + d] + selu_f(outv[b * DD + d] * invn);
        s1 += v[i]; s2 += v[i] * v[i];
    }
    s1 = warpSum(s1); s2 = warpSum(s2);
    if ((t & 31) == 0) { red[t >> 5] = s1; red[8 + (t >> 5)] = s2; }
    __syncthreads();
    s1 = 0.f; s2 = 0.f;
    #pragma unroll
    for (int w = 0; w < 8; w++) { s1 += red[w]; s2 += red[8 + w]; }
    float mu = s1 / (float)DD;
    float var = fmaxf(s2 / (float)DD - mu * mu, 0.f);
    float rstd = rsqrtf(var + 1e-5f);
    #pragma unroll
    for (int i = 0; i < 4; i++) {
        int d = i * 256 + t;
        qdst[b * DD + d] = (v[i] - mu) * rstd * lnw[d] + lnb[d];
    }
}

// ---------------- the one persistent megakernel ----------------
__global__ void __launch_bounds__(256, 4)
mega(const float* __restrict__ query, const float* __restrict__ feat,
     const float* __restrict__ Wh, const float* __restrict__ Wf,
     const float* __restrict__ Wg, const float* __restrict__ lnw,
     const float* __restrict__ lnb, const float* __restrict__ Wout,
     const float* __restrict__ bout, const unsigned* __restrict__ mask,
     float* __restrict__ out) {
    __shared__ __align__(16) char smraw[37888];
    unsigned sense = g_bar_sense;   // read before any block can flip it
    int bid = blockIdx.x;
    const float INVN = 1.0f / (float)NN;

    // ---- S1: Wgm = mean_g W_g ----
    {
        const float4* W = (const float4*)Wg;
        int i0 = bid * 512 + threadIdx.x;
        #pragma unroll
        for (int r = 0; r < 2; r++) {
            int i = i0 + r * 256;
            float4 a = __ldcs(W + i), b4 = __ldcs(W + i + 262144),
                   c4 = __ldcs(W + i + 524288), d4 = __ldcs(W + i + 786432);
            float4 rr;
            rr.x = 0.25f * (a.x + b4.x + c4.x + d4.x);
            rr.y = 0.25f * (a.y + b4.y + c4.y + d4.y);
            rr.z = 0.25f * (a.z + b4.z + c4.z + d4.z);
            rr.w = 0.25f * (a.w + b4.w + c4.w + d4.w);
            ((float4*)g_Wgm)[i] = rr;
        }
    }
    gbar(sense);

    // ---- S2: q0 = query @ W_h (0..63) | b from mask + softmax (64..71) ----
    if (bid < 64) {
        colmv_plain(Wh, query, g_qA, bid);
    } else if (bid < 72) {
        int b = bid - 64, t = threadIdx.x;
        float v[16];
        #pragma unroll
        for (int i = 0; i < 16; i++) {
            float bv = (mask[b * NN + i * 256 + t] != 0u) ? -1e18f : 0.0f;
            g_b[b * NN + i * 256 + t] = bv;
            v[i] = bv;
        }
        softmax_store(b, v);
    }
    gbar(sense);

    // ======== iteration 0 (q = q0 in g_qA) ========
    if (bid < 64) colmv_plain(g_Wgm, g_qA, g_tmp, bid);      // tmp = Wgm^T q0
    gbar(sense);
    rowdot(Wf, g_tmp, g_qt, nullptr, smraw);                 // qt = W_f tmp
    gbar(sense);
    pass_phase(feat, 1, smraw);                              // delta, s-partials
    gbar(sense);
    if (bid < 64) colmv_s(Wf, g_tmp2, bid);                  // tmp2 = W_f^T s
    else if (bid < 72) bupd(bid - 64);                       // b+=norm(delta); c
    gbar(sense);
    rowdot(g_Wgm, g_tmp2, g_outv, nullptr, smraw);           // outv0 = Wgm tmp2
    gbar(sense);

    // ======== iteration 1 (q1 = LN(q0+selu(outv0/n)) inline) ========
    if (bid < 64) colmv_q(g_Wgm, g_qA, g_outv, lnw, lnb, INVN,
                          (bid == 0), g_qB, g_tmp, bid);     // tmp = Wgm^T q1
    gbar(sense);
    rowdot(Wf, g_tmp, g_qt, nullptr, smraw);                 // qt = W_f tmp
    gbar(sense);
    pass_phase(feat, 1, smraw);
    gbar(sense);
    if (bid < 64) colmv_s(Wf, g_tmp2, bid);
    else if (bid < 72) bupd(bid - 64);
    gbar(sense);
    rowdot(g_Wgm, g_tmp2, g_outv, nullptr, smraw);           // outv1
    gbar(sense);

    // ======== iteration 2 (last; uses c2 from it1's bupd, no qt/delta) ========
    pass_phase(feat, 0, smraw);                              // s-partials only
    gbar(sense);
    if (bid < 64) colmv_s(Wf, g_tmp2, bid);                  // tmp2 = W_f^T s
    else if (bid < 72) qupd_block(bid - 64, g_qB, g_outv,
                                  lnw, lnb, INVN, g_qA);     // q2 -> g_qA
    gbar(sense);
    rowdot(g_Wgm, g_tmp2, g_outv, nullptr, smraw);           // outv2
    gbar(sense);
    // out = LN(q2 + selu(outv2)) @ W_out^T + b_out   (q3 inline)
    rowdot_q(Wout, g_qA, g_outv, lnw, lnb, out, bout, smraw);
}

// ---------------- host orchestration: ONE launch ----------------
extern "C" void kernel_launch(void* const* d_in, const int* in_sizes, int n_in,
                              void* d_out, int out_size) {
    const float* query = (const float*)d_in[0];
    const float* feat  = (const float*)d_in[1];
    const float* W_h   = (const float*)d_in[2];
    const float* W_f   = (const float*)d_in[3];
    const float* W_g   = (const float*)d_in[4];
    const float* ln_w  = (const float*)d_in[5];
    const float* ln_b  = (const float*)d_in[6];
    const float* W_out = (const float*)d_in[7];
    const float* b_out = (const float*)d_in[8];
    const unsigned* mask = (const unsigned*)d_in[9];
    float* out = (float*)d_out;

    mega<<<NB, 256>>>(query, feat, W_h, W_f, W_g, ln_w, ln_b, W_out, b_out,
                      mask, out);
}

// round 12
// speedup vs baseline: 1.0349x; 1.0349x over previous
#include <cuda_runtime.h>

#define BB 8
#define NN 4096
#define DD 1024
#define NB 512          // all resident: 512 <= 4 * 148 SMs
#define KS 16           // k-slices in column-GEMV
#define DT 4            // d-tiles in column-GEMV

// ---------------- device scratch (no allocations allowed) ----------------
__device__ __align__(16) float g_Wgm[DD * DD];
__device__ __align__(16) float g_b[BB * NN];
__device__ __align__(16) float g_c[BB * NN];
__device__ __align__(16) float g_delta[BB * NN];
__device__ __align__(16) float g_qA[BB * DD];    // holds q0, later q2
__device__ __align__(16) float g_qB[BB * DD];    // holds q1
__device__ __align__(16) float g_tmp[BB * DD];
__device__ __align__(16) float g_tmp2[BB * DD];
__device__ __align__(16) float g_qt[BB * DD];
__device__ __align__(16) float g_outv[BB * DD];
__device__ __align__(16) float g_part[BB * 64 * DD];
__device__ __align__(16) float g_cpart[KS * BB * DD];
__device__ unsigned g_cnt[DT];        // zero-init, self-resetting
__device__ unsigned g_bar_count;      // zero-init, self-resetting
__device__ unsigned g_bar_sense;      // read at kernel start (any parity ok)

// ---------------- helpers ----------------
__device__ __forceinline__ float warpSum(float v) {
    #pragma unroll
    for (int o = 16; o; o >>= 1) v += __shfl_xor_sync(0xffffffffu, v, o);
    return v;
}
__device__ __forceinline__ float warpMax(float v) {
    #pragma unroll
    for (int o = 16; o; o >>= 1) v = fmaxf(v, __shfl_xor_sync(0xffffffffu, v, o));
    return v;
}
__device__ __forceinline__ float selu_f(float x) {
    const float A = 1.6732632423543772f, S = 1.0507009873554805f;
    return (x > 0.f) ? S * x : S * A * expm1f(x);
}

// grid-wide sense-reversing barrier; all NB blocks call it equally often.
__device__ __forceinline__ void gbar(unsigned& sense) {
    __threadfence();
    __syncthreads();
    sense ^= 1u;
    if (threadIdx.x == 0) {
        unsigned a = atomicAdd(&g_bar_count, 1u);
        if (a == NB - 1) {
            g_bar_count = 0;
            __threadfence();
            atomicExch(&g_bar_sense, sense);
        } else {
            while (*(volatile unsigned*)&g_bar_sense != sense) __nanosleep(32);
        }
    }
    __syncthreads();
    __threadfence();
}

// softmax over 4096 values held 16/thread in v[]; writes g_c[b]. 256 threads.
__device__ void softmax_store(int b, float* v) {
    __shared__ float red[8];
    int t = threadIdx.x;
    float mx = -3.0e38f;
    #pragma unroll
    for (int i = 0; i < 16; i++) mx = fmaxf(mx, v[i]);
    mx = warpMax(mx);
    if ((t & 31) == 0) red[t >> 5] = mx;
    __syncthreads();
    mx = red[0];
    #pragma unroll
    for (int w = 1; w < 8; w++) mx = fmaxf(mx, red[w]);
    float sum = 0.f;
    #pragma unroll
    for (int i = 0; i < 16; i++) { v[i] = expf(v[i] - mx); sum += v[i]; }
    sum = warpSum(sum);
    __syncthreads();
    if ((t & 31) == 0) red[t >> 5] = sum;
    __syncthreads();
    sum = 0.f;
    #pragma unroll
    for (int w = 0; w < 8; w++) sum += red[w];
    float inv = 1.0f / sum;
    #pragma unroll
    for (int i = 0; i < 16; i++) g_c[b * NN + i * 256 + t] = v[i] * inv;
}

// per-warp LN stats for batch b over v(d) = qold[d] + selu(outv[d]*invn)
__device__ __forceinline__ void q_stats(const float* __restrict__ qold,
                                        const float* __restrict__ outv,
                                        int b, float invn, int lane,
                                        float& mu, float& rstd) {
    float s1 = 0.f, s2 = 0.f;
    #pragma unroll 8
    for (int k = 0; k < 32; k++) {
        int d = k * 32 + lane;
        float v = qold[b * DD + d] + selu_f(outv[b * DD + d] * invn);
        s1 += v; s2 += v * v;
    }
    s1 = warpSum(s1); s2 = warpSum(s2);
    mu = s1 / (float)DD;
    float var = fmaxf(s2 / (float)DD - mu * mu, 0.f);
    rstd = rsqrtf(var + 1e-5f);
}

// shared compute tail of the split-K column-GEMV. sx[b][64] in smem.
__device__ void colmv_compute(const float* __restrict__ M,
                              const float sx[BB][64], float* __restrict__ Y,
                              int dt, int ks) {
    __shared__ unsigned done;
    int d = dt * 256 + threadIdx.x;
    float acc[BB];
    #pragma unroll
    for (int b = 0; b < BB; b++) acc[b] = 0.f;
    const float* Mp = M + (size_t)(ks * 64) * DD + d;
    #pragma unroll 8
    for (int k = 0; k < 64; k++) {
        float m = Mp[(size_t)k * DD];
        #pragma unroll
        for (int b = 0; b < BB; b++) acc[b] += sx[b][k] * m;
    }
    #pragma unroll
    for (int b = 0; b < BB; b++) g_cpart[(ks * BB + b) * DD + d] = acc[b];
    __threadfence();
    __syncthreads();
    if (threadIdx.x == 0) done = atomicAdd(&g_cnt[dt], 1u);
    __syncthreads();
    if (done == KS - 1) {
        #pragma unroll
        for (int b = 0; b < BB; b++) {
            float s = 0.f;
            #pragma unroll
            for (int k2 = 0; k2 < KS; k2++)
                s += __ldcg(&g_cpart[(k2 * BB + b) * DD + d]);
            Y[b * DD + d] = s;
        }
        __syncthreads();
        if (threadIdx.x == 0) g_cnt[dt] = 0;
    }
}

// plain column-GEMV: X read from global
__device__ void colmv_plain(const float* __restrict__ M, const float* __restrict__ X,
                            float* __restrict__ Y, int cb) {
    __shared__ float sx[BB][64];
    int dt = cb & (DT - 1), ks = cb >> 2;
    for (int i = threadIdx.x; i < BB * 64; i += 256)
        sx[i >> 6][i & 63] = X[(i >> 6) * DD + ks * 64 + (i & 63)];
    __syncthreads();
    colmv_compute(M, sx, Y, dt, ks);
}

// column-GEMV with inline q-update: X = LN(qold + selu(outv*invn)).
__device__ void colmv_q(const float* __restrict__ M,
                        const float* __restrict__ qold,
                        const float* __restrict__ outv,
                        const float* __restrict__ lnw,
                        const float* __restrict__ lnb,
                        float invn, int write_q, float* __restrict__ qdst,
                        float* __restrict__ Y, int cb) {
    __shared__ float sx[BB][64];
    int warp = threadIdx.x >> 5, lane = threadIdx.x & 31;
    int dt = cb & (DT - 1), ks = cb >> 2;
    float mu, rstd;
    q_stats(qold, outv, warp, invn, lane, mu, rstd);
    #pragma unroll
    for (int j = 0; j < 2; j++) {
        int d = ks * 64 + j * 32 + lane;
        float v = qold[warp * DD + d] + selu_f(outv[warp * DD + d] * invn);
        sx[warp][j * 32 + lane] = (v - mu) * rstd * lnw[d] + lnb[d];
    }
    if (write_q) {
        #pragma unroll 4
        for (int k = 0; k < 32; k++) {
            int d = k * 32 + lane;
            float v = qold[warp * DD + d] + selu_f(outv[warp * DD + d] * invn);
            qdst[warp * DD + d] = (v - mu) * rstd * lnw[d] + lnb[d];
        }
    }
    __syncthreads();
    colmv_compute(M, sx, Y, dt, ks);
}

// column-GEMV fused with s-reduction: X[b,k] = sum over 64 chunks of g_part.
__device__ void colmv_s(const float* __restrict__ M, float* __restrict__ Y, int cb) {
    __shared__ float sx[BB][64];
    int dt = cb & (DT - 1), ks = cb >> 2;
    #pragma unroll
    for (int p = 0; p < 2; p++) {
        int idx = p * 256 + threadIdx.x;
        int b = idx >> 6, kk = idx & 63;
        const float* pp = g_part + (size_t)(b * 64) * DD + ks * 64 + kk;
        float a0 = 0.f, a1 = 0.f, a2 = 0.f, a3 = 0.f;
        #pragma unroll 4
        for (int c = 0; c < 64; c += 4) {
            a0 += pp[(size_t)c * DD];
            a1 += pp[(size_t)(c + 1) * DD];
            a2 += pp[(size_t)(c + 2) * DD];
            a3 += pp[(size_t)(c + 3) * DD];
        }
        sx[b][kk] = (a0 + a1) + (a2 + a3);
    }
    __syncthreads();
    colmv_compute(M, sx, Y, dt, ks);
}

// row-dot matvec over all NB blocks: Y[b,r] = dot(M[r,:], X[b,:]) (+bias).
__device__ void rowdot(const float* __restrict__ M, const float* __restrict__ X,
                       float* __restrict__ Y, const float* __restrict__ bias,
                       char* smraw) {
    float4* shX = (float4*)smraw;                  // 2048 f4 = 32 KB
    const float4* Xv = (const float4*)X;
    #pragma unroll
    for (int i = threadIdx.x; i < BB * DD / 4; i += 256) shX[i] = Xv[i];
    __syncthreads();
    int warp = threadIdx.x >> 5, lane = threadIdx.x & 31;
    int row = blockIdx.x * 2 + (warp & 1);
    int b0 = (warp >> 1) * 2;
    const float4* Mr = (const float4*)(M + (size_t)row * DD);
    float a0 = 0.f, a1 = 0.f;
    #pragma unroll
    for (int j = 0; j < 8; j++) {
        float4 m = Mr[j * 32 + lane];
        float4 x0 = shX[b0 * 256 + j * 32 + lane];
        float4 x1 = shX[(b0 + 1) * 256 + j * 32 + lane];
        a0 += m.x * x0.x + m.y * x0.y + m.z * x0.z + m.w * x0.w;
        a1 += m.x * x1.x + m.y * x1.y + m.z * x1.z + m.w * x1.w;
    }
    a0 = warpSum(a0); a1 = warpSum(a1);
    if (lane == 0) {
        float bo = bias ? bias[row] : 0.f;
        Y[(size_t)b0 * DD + row] = a0 + bo;
        Y[(size_t)(b0 + 1) * DD + row] = a1 + bo;
    }
    __syncthreads();
}

// final row-dot with inline q-update: X = LN(qold + selu(outv)).
__device__ void rowdot_q(const float* __restrict__ M,
                         const float* __restrict__ qold,
                         const float* __restrict__ outv,
                         const float* __restrict__ lnw,
                         const float* __restrict__ lnb,
                         float* __restrict__ Y, const float* __restrict__ bias,
                         char* smraw) {
    float* shX = (float*)smraw;                    // [8][1024] = 32 KB
    int warp = threadIdx.x >> 5, lane = threadIdx.x & 31;
    float mu, rstd;
    q_stats(qold, outv, warp, 1.0f, lane, mu, rstd);
    #pragma unroll 4
    for (int k = 0; k < 32; k++) {
        int d = k * 32 + lane;
        float v = qold[warp * DD + d] + selu_f(outv[warp * DD + d]);
        shX[warp * DD + d] = (v - mu) * rstd * lnw[d] + lnb[d];
    }
    __syncthreads();
    int row = blockIdx.x * 2 + (warp & 1);
    int b0 = (warp >> 1) * 2;
    const float4* Mr = (const float4*)(M + (size_t)row * DD);
    const float4* x0p = (const float4*)(shX + b0 * DD);
    const float4* x1p = (const float4*)(shX + (b0 + 1) * DD);
    float a0 = 0.f, a1 = 0.f;
    #pragma unroll
    for (int j = 0; j < 8; j++) {
        float4 m = Mr[j * 32 + lane];
        float4 x0 = x0p[j * 32 + lane];
        float4 x1 = x1p[j * 32 + lane];
        a0 += m.x * x0.x + m.y * x0.y + m.z * x0.z + m.w * x0.w;
        a1 += m.x * x1.x + m.y * x1.y + m.z * x1.z + m.w * x1.w;
    }
    a0 = warpSum(a0); a1 = warpSum(a1);
    if (lane == 0) {
        float bo = bias[row];
        Y[(size_t)b0 * DD + row] = a0 + bo;
        Y[(size_t)(b0 + 1) * DD + row] = a1 + bo;
    }
}

// ---------------- big streaming pass with cp.async double buffering --------
// 512 blocks = (batch b = bid>>6, chunk = bid&63). 64 rows per block,
// 16 stages x 4 rows (16 KB contiguous), 2 smem buffers.
// Warp w: row (w>>1) of the stage, half (w&1) of the row.
#define PASS_PREFETCH(st) do {                                            \
    unsigned dstb = smbuf_u32 + (((st) & 1) ? 16384u : 0u);               \
    const float4* srcp = fb + (size_t)(st) * 1024;                        \
    _Pragma("unroll")                                                     \
    for (int j = 0; j < 4; j++) {                                         \
        unsigned da = dstb + (threadIdx.x + j * 256) * 16u;               \
        asm volatile("cp.async.cg.shared.global [%0], [%1], 16;"          \
                     :: "r"(da), "l"(srcp + threadIdx.x + j * 256));      \
    }                                                                     \
    asm volatile("cp.async.commit_group;");                               \
} while (0)

__device__ void pass_phase(const float* __restrict__ feat, int want_delta,
                           char* smraw) {
    float4* buf   = (float4*)smraw;               // [2][1024] f4 = 32 KB
    float4* sh_s  = (float4*)(smraw + 32768);     // 256 f4 = 4 KB
    float*  sh_c  = (float*)(smraw + 36864);      // 64 floats
    float*  sh_dp = (float*)(smraw + 37120);      // 16*8 floats
    unsigned smbuf_u32 = (unsigned)__cvta_generic_to_shared(buf);

    int b = blockIdx.x >> 6, chunk = blockIdx.x & 63;
    int warp = threadIdx.x >> 5, lane = threadIdx.x & 31;
    int row = warp >> 1, half = warp & 1;
    int cbase = half * 128 + lane;                // column float4 index base
    int rbase = row * 256 + cbase;                // within-stage float4 index

    if (threadIdx.x < 64) sh_c[threadIdx.x] = g_c[b * NN + chunk * 64 + threadIdx.x];
    const float4* qtv = (const float4*)(g_qt + b * DD);
    float4 q0 = qtv[cbase], q1 = qtv[cbase + 32],
           q2 = qtv[cbase + 64], q3 = qtv[cbase + 96];
    float4 s0 = make_float4(0.f, 0.f, 0.f, 0.f), s1 = s0, s2 = s0, s3 = s0;

    const float4* fb = (const float4*)feat + ((size_t)b * NN + chunk * 64) * 256;

    PASS_PREFETCH(0);
    PASS_PREFETCH(1);

    for (int s = 0; s < 16; s++) {
        if (s < 15) asm volatile("cp.async.wait_group 1;");
        else        asm volatile("cp.async.wait_group 0;");
        __syncthreads();                      // stage s ready; prev compute done
        const float4* rp = buf + ((s & 1) ? 1024 : 0) + rbase;
        float4 v0 = rp[0], v1 = rp[32], v2 = rp[64], v3 = rp[96];
        float cw = sh_c[s * 4 + row];
        if (want_delta) {
            float dp = v0.x*q0.x + v0.y*q0.y + v0.z*q0.z + v0.w*q0.w
                     + v1.x*q1.x + v1.y*q1.y + v1.z*q1.z + v1.w*q1.w
                     + v2.x*q2.x + v2.y*q2.y + v2.z*q2.z + v2.w*q2.w
                     + v3.x*q3.x + v3.y*q3.y + v3.z*q3.z + v3.w*q3.w;
            dp = warpSum(dp);
            if (lane == 0) sh_dp[s * 8 + row * 2 + half] = dp;
        }
        s0.x += cw*v0.x; s0.y += cw*v0.y; s0.z += cw*v0.z; s0.w += cw*v0.w;
        s1.x += cw*v1.x; s1.y += cw*v1.y; s1.z += cw*v1.z; s1.w += cw*v1.w;
        s2.x += cw*v2.x; s2.y += cw*v2.y; s2.z += cw*v2.z; s2.w += cw*v2.w;
        s3.x += cw*v3.x; s3.y += cw*v3.y; s3.z += cw*v3.z; s3.w += cw*v3.w;
        __syncthreads();                      // all done reading buf[s&1]
        if (s + 2 < 16) PASS_PREFETCH(s + 2);
    }

    if (want_delta && threadIdx.x < 64) {
        int st = threadIdx.x >> 2, r = threadIdx.x & 3;
        g_delta[b * NN + chunk * 64 + threadIdx.x] =
            sh_dp[st * 8 + r * 2] + sh_dp[st * 8 + r * 2 + 1];
    }
    // staggered deterministic s-reduce: 4 warps per half (rows 0..3)
    #pragma unroll
    for (int w = 0; w < 4; w++) {
        if (row == w) {
            if (w == 0) {
                sh_s[cbase] = s0; sh_s[cbase + 32] = s1;
                sh_s[cbase + 64] = s2; sh_s[cbase + 96] = s3;
            } else {
                float4 t;
                t = sh_s[cbase];      t.x+=s0.x; t.y+=s0.y; t.z+=s0.z; t.w+=s0.w; sh_s[cbase]      = t;
                t = sh_s[cbase + 32]; t.x+=s1.x; t.y+=s1.y; t.z+=s1.z; t.w+=s1.w; sh_s[cbase + 32] = t;
                t = sh_s[cbase + 64]; t.x+=s2.x; t.y+=s2.y; t.z+=s2.z; t.w+=s2.w; sh_s[cbase + 64] = t;
                t = sh_s[cbase + 96]; t.x+=s3.x; t.y+=s3.y; t.z+=s3.z; t.w+=s3.w; sh_s[cbase + 96] = t;
            }
        }
        __syncthreads();
    }
    float4* pp = (float4*)(g_part + ((size_t)b * 64 + chunk) * DD);
    pp[threadIdx.x] = sh_s[threadIdx.x];
    __syncthreads();
}

// b += standardize(delta, ddof=1), then c = softmax(b). One block per batch.
__device__ void bupd(int b) {
    __shared__ float red2[16];
    int t = threadIdx.x;
    float v[16];
    float s1 = 0.f, s2 = 0.f;
    #pragma unroll
    for (int i = 0; i < 16; i++) {
        v[i] = g_delta[b * NN + i * 256 + t];
        s1 += v[i]; s2 += v[i] * v[i];
    }
    s1 = warpSum(s1); s2 = warpSum(s2);
    if ((t & 31) == 0) { red2[t >> 5] = s1; red2[8 + (t >> 5)] = s2; }
    __syncthreads();
    s1 = 0.f; s2 = 0.f;
    #pragma unroll
    for (int w = 0; w < 8; w++) { s1 += red2[w]; s2 += red2[8 + w]; }
    float mean = s1 / (float)NN;
    float var = fmaxf((s2 - s1 * s1 / (float)NN) / (float)(NN - 1), 0.f);
    float inv = 1.0f / (sqrtf(var) + 1e-9f);
    #pragma unroll
    for (int i = 0; i < 16; i++) {
        float nb = g_b[b * NN + i * 256 + t] + (v[i] - mean) * inv;
        g_b[b * NN + i * 256 + t] = nb;
        v[i] = nb;
    }
    __syncthreads();
    softmax_store(b, v);
}

// standalone q-update for one batch: qdst = LN(qold+selu(outv*invn))
__device__ void qupd_block(int b, const float* __restrict__ qold,
                           const float* __restrict__ outv,
                           const float* __restrict__ lnw,
                           const float* __restrict__ lnb,
                           float invn, float* __restrict__ qdst) {
    __shared__ float red[16];
    int t = threadIdx.x;
    float v[4];
    float s1 = 0.f, s2 = 0.f;
    #pragma unroll
    for (int i = 0; i < 4; i++) {
        int d = i * 256 + t;
        v[i] = qold[b * DD + d] + selu_f(outv[b * DD + d] * invn);
        s1 += v[i]; s2 += v[i] * v[i];
    }
    s1 = warpSum(s1); s2 = warpSum(s2);
    if ((t & 31) == 0) { red[t >> 5] = s1; red[8 + (t >> 5)] = s2; }
    __syncthreads();
    s1 = 0.f; s2 = 0.f;
    #pragma unroll
    for (int w = 0; w < 8; w++) { s1 += red[w]; s2 += red[8 + w]; }
    float mu = s1 / (float)DD;
    float var = fmaxf(s2 / (float)DD - mu * mu, 0.f);
    float rstd = rsqrtf(var + 1e-5f);
    #pragma unroll
    for (int i = 0; i < 4; i++) {
        int d = i * 256 + t;
        qdst[b * DD + d] = (v[i] - mu) * rstd * lnw[d] + lnb[d];
    }
}

// ---------------- the one persistent megakernel ----------------
__global__ void __launch_bounds__(256, 4)
mega(const float* __restrict__ query, const float* __restrict__ feat,
     const float* __restrict__ Wh, const float* __restrict__ Wf,
     const float* __restrict__ Wg, const float* __restrict__ lnw,
     const float* __restrict__ lnb, const float* __restrict__ Wout,
     const float* __restrict__ bout, const unsigned* __restrict__ mask,
     float* __restrict__ out) {
    __shared__ __align__(16) char smraw[37888];
    unsigned sense = g_bar_sense;   // read before any block can flip it
    int bid = blockIdx.x;
    const float INVN = 1.0f / (float)NN;

    // ---- S1: Wgm = mean_g W_g ----
    {
        const float4* W = (const float4*)Wg;
        int i0 = bid * 512 + threadIdx.x;
        #pragma unroll
        for (int r = 0; r < 2; r++) {
            int i = i0 + r * 256;
            float4 a = __ldcs(W + i), b4 = __ldcs(W + i + 262144),
                   c4 = __ldcs(W + i + 524288), d4 = __ldcs(W + i + 786432);
            float4 rr;
            rr.x = 0.25f * (a.x + b4.x + c4.x + d4.x);
            rr.y = 0.25f * (a.y + b4.y + c4.y + d4.y);
            rr.z = 0.25f * (a.z + b4.z + c4.z + d4.z);
            rr.w = 0.25f * (a.w + b4.w + c4.w + d4.w);
            ((float4*)g_Wgm)[i] = rr;
        }
    }
    gbar(sense);

    // ---- S2: q0 = query @ W_h (0..63) | b from mask + softmax (64..71) ----
    if (bid < 64) {
        colmv_plain(Wh, query, g_qA, bid);
    } else if (bid < 72) {
        int b = bid - 64, t = threadIdx.x;
        float v[16];
        #pragma unroll
        for (int i = 0; i < 16; i++) {
            float bv = (mask[b * NN + i * 256 + t] != 0u) ? -1e18f : 0.0f;
            g_b[b * NN + i * 256 + t] = bv;
            v[i] = bv;
        }
        softmax_store(b, v);
    }
    gbar(sense);

    // ======== iteration 0 (q = q0 in g_qA) ========
    if (bid < 64) colmv_plain(g_Wgm, g_qA, g_tmp, bid);      // tmp = Wgm^T q0
    gbar(sense);
    rowdot(Wf, g_tmp, g_qt, nullptr, smraw);                 // qt = W_f tmp
    gbar(sense);
    pass_phase(feat, 1, smraw);                              // delta, s-partials
    gbar(sense);
    if (bid < 64) colmv_s(Wf, g_tmp2, bid);                  // tmp2 = W_f^T s
    else if (bid < 72) bupd(bid - 64);                       // b+=norm(delta); c
    gbar(sense);
    rowdot(g_Wgm, g_tmp2, g_outv, nullptr, smraw);           // outv0 = Wgm tmp2
    gbar(sense);

    // ======== iteration 1 (q1 = LN(q0+selu(outv0/n)) inline) ========
    if (bid < 64) colmv_q(g_Wgm, g_qA, g_outv, lnw, lnb, INVN,
                          (bid == 0), g_qB, g_tmp, bid);     // tmp = Wgm^T q1
    gbar(sense);
    rowdot(Wf, g_tmp, g_qt, nullptr, smraw);                 // qt = W_f tmp
    gbar(sense);
    pass_phase(feat, 1, smraw);
    gbar(sense);
    if (bid < 64) colmv_s(Wf, g_tmp2, bid);
    else if (bid < 72) bupd(bid - 64);
    gbar(sense);
    rowdot(g_Wgm, g_tmp2, g_outv, nullptr, smraw);           // outv1
    gbar(sense);

    // ======== iteration 2 (last; uses c2 from it1's bupd, no qt/delta) ========
    pass_phase(feat, 0, smraw);                              // s-partials only
    gbar(sense);
    if (bid < 64) colmv_s(Wf, g_tmp2, bid);                  // tmp2 = W_f^T s
    else if (bid < 72) qupd_block(bid - 64, g_qB, g_outv,
                                  lnw, lnb, INVN, g_qA);     // q2 -> g_qA
    gbar(sense);
    rowdot(g_Wgm, g_tmp2, g_outv, nullptr, smraw);           // outv2
    gbar(sense);
    // out = LN(q2 + selu(outv2)) @ W_out^T + b_out   (q3 inline)
    rowdot_q(Wout, g_qA, g_outv, lnw, lnb, out, bout, smraw);
}

// ---------------- host orchestration: ONE launch ----------------
extern "C" void kernel_launch(void* const* d_in, const int* in_sizes, int n_in,
                              void* d_out, int out_size) {
    const float* query = (const float*)d_in[0];
    const float* feat  = (const float*)d_in[1];
    const float* W_h   = (const float*)d_in[2];
    const float* W_f   = (const float*)d_in[3];
    const float* W_g   = (const float*)d_in[4];
    const float* ln_w  = (const float*)d_in[5];
    const float* ln_b  = (const float*)d_in[6];
    const float* W_out = (const float*)d_in[7];
    const float* b_out = (const float*)d_in[8];
    const unsigned* mask = (const unsigned*)d_in[9];
    float* out = (float*)d_out;

    mega<<<NB, 256>>>(query, feat, W_h, W_f, W_g, ln_w, ln_b, W_out, b_out,
                      mask, out);
}

// round 13
// speedup vs baseline: 1.0415x; 1.0064x over previous
#include <cuda_runtime.h>

#define BB 8
#define NN 4096
#define DD 1024
#define NB 512          // all resident: 512 <= 4 * 148 SMs
#define KS 16           // k-slices in column-GEMV
#define DT 4            // d-tiles in column-GEMV

// ---------------- device scratch (no allocations allowed) ----------------
__device__ __align__(16) float g_Wgm[DD * DD];
__device__ __align__(16) float g_b[BB * NN];
__device__ __align__(16) float g_c[BB * NN];
__device__ __align__(16) float g_delta[BB * NN];
__device__ __align__(16) float g_qA[BB * DD];    // holds q0, later q2
__device__ __align__(16) float g_qB[BB * DD];    // holds q1
__device__ __align__(16) float g_tmp[BB * DD];
__device__ __align__(16) float g_tmp2[BB * DD];
__device__ __align__(16) float g_qt[BB * DD];
__device__ __align__(16) float g_outv[BB * DD];
__device__ __align__(16) float g_part[BB * 64 * DD];
__device__ __align__(16) float g_cpart[KS * BB * DD];
__device__ unsigned g_cnt[DT];        // zero-init, self-resetting
__device__ unsigned g_bar_count;      // zero-init, self-resetting
__device__ unsigned g_bar_sense;      // read at kernel start (any parity ok)

// ---------------- helpers ----------------
__device__ __forceinline__ float warpSum(float v) {
    #pragma unroll
    for (int o = 16; o; o >>= 1) v += __shfl_xor_sync(0xffffffffu, v, o);
    return v;
}
__device__ __forceinline__ float warpMax(float v) {
    #pragma unroll
    for (int o = 16; o; o >>= 1) v = fmaxf(v, __shfl_xor_sync(0xffffffffu, v, o));
    return v;
}
__device__ __forceinline__ float selu_f(float x) {
    const float A = 1.6732632423543772f, S = 1.0507009873554805f;
    return (x > 0.f) ? S * x : S * A * expm1f(x);
}

// grid-wide sense-reversing barrier; all NB blocks call it equally often.
__device__ __forceinline__ void gbar(unsigned& sense) {
    __threadfence();
    __syncthreads();
    sense ^= 1u;
    if (threadIdx.x == 0) {
        unsigned a = atomicAdd(&g_bar_count, 1u);
        if (a == NB - 1) {
            g_bar_count = 0;
            __threadfence();
            atomicExch(&g_bar_sense, sense);
        } else {
            while (*(volatile unsigned*)&g_bar_sense != sense) __nanosleep(32);
        }
    }
    __syncthreads();
    __threadfence();
}

// softmax over 4096 values held 16/thread in v[]; writes g_c[b]. 256 threads.
__device__ void softmax_store(int b, float* v) {
    __shared__ float red[8];
    int t = threadIdx.x;
    float mx = -3.0e38f;
    #pragma unroll
    for (int i = 0; i < 16; i++) mx = fmaxf(mx, v[i]);
    mx = warpMax(mx);
    if ((t & 31) == 0) red[t >> 5] = mx;
    __syncthreads();
    mx = red[0];
    #pragma unroll
    for (int w = 1; w < 8; w++) mx = fmaxf(mx, red[w]);
    float sum = 0.f;
    #pragma unroll
    for (int i = 0; i < 16; i++) { v[i] = expf(v[i] - mx); sum += v[i]; }
    sum = warpSum(sum);
    __syncthreads();
    if ((t & 31) == 0) red[t >> 5] = sum;
    __syncthreads();
    sum = 0.f;
    #pragma unroll
    for (int w = 0; w < 8; w++) sum += red[w];
    float inv = 1.0f / sum;
    #pragma unroll
    for (int i = 0; i < 16; i++) g_c[b * NN + i * 256 + t] = v[i] * inv;
}

// per-warp LN stats for batch b over v(d) = qold[d] + selu(outv[d]*invn)
__device__ __forceinline__ void q_stats(const float* __restrict__ qold,
                                        const float* __restrict__ outv,
                                        int b, float invn, int lane,
                                        float& mu, float& rstd) {
    float s1 = 0.f, s2 = 0.f;
    #pragma unroll 8
    for (int k = 0; k < 32; k++) {
        int d = k * 32 + lane;
        float v = qold[b * DD + d] + selu_f(outv[b * DD + d] * invn);
        s1 += v; s2 += v * v;
    }
    s1 = warpSum(s1); s2 = warpSum(s2);
    mu = s1 / (float)DD;
    float var = fmaxf(s2 / (float)DD - mu * mu, 0.f);
    rstd = rsqrtf(var + 1e-5f);
}

// shared compute tail of the split-K column-GEMV. sx[b][64] in smem.
__device__ void colmv_compute(const float* __restrict__ M,
                              const float sx[BB][64], float* __restrict__ Y,
                              int dt, int ks) {
    __shared__ unsigned done;
    int d = dt * 256 + threadIdx.x;
    float acc[BB];
    #pragma unroll
    for (int b = 0; b < BB; b++) acc[b] = 0.f;
    const float* Mp = M + (size_t)(ks * 64) * DD + d;
    #pragma unroll 8
    for (int k = 0; k < 64; k++) {
        float m = Mp[(size_t)k * DD];
        #pragma unroll
        for (int b = 0; b < BB; b++) acc[b] += sx[b][k] * m;
    }
    #pragma unroll
    for (int b = 0; b < BB; b++) g_cpart[(ks * BB + b) * DD + d] = acc[b];
    __threadfence();
    __syncthreads();
    if (threadIdx.x == 0) done = atomicAdd(&g_cnt[dt], 1u);
    __syncthreads();
    if (done == KS - 1) {
        #pragma unroll
        for (int b = 0; b < BB; b++) {
            float s = 0.f;
            #pragma unroll
            for (int k2 = 0; k2 < KS; k2++)
                s += __ldcg(&g_cpart[(k2 * BB + b) * DD + d]);
            Y[b * DD + d] = s;
        }
        __syncthreads();
        if (threadIdx.x == 0) g_cnt[dt] = 0;
    }
}

// plain column-GEMV: X read from global
__device__ void colmv_plain(const float* __restrict__ M, const float* __restrict__ X,
                            float* __restrict__ Y, int cb) {
    __shared__ float sx[BB][64];
    int dt = cb & (DT - 1), ks = cb >> 2;
    for (int i = threadIdx.x; i < BB * 64; i += 256)
        sx[i >> 6][i & 63] = X[(i >> 6) * DD + ks * 64 + (i & 63)];
    __syncthreads();
    colmv_compute(M, sx, Y, dt, ks);
}

// column-GEMV with inline q-update: X = LN(qold + selu(outv*invn)).
__device__ void colmv_q(const float* __restrict__ M,
                        const float* __restrict__ qold,
                        const float* __restrict__ outv,
                        const float* __restrict__ lnw,
                        const float* __restrict__ lnb,
                        float invn, int write_q, float* __restrict__ qdst,
                        float* __restrict__ Y, int cb) {
    __shared__ float sx[BB][64];
    int warp = threadIdx.x >> 5, lane = threadIdx.x & 31;
    int dt = cb & (DT - 1), ks = cb >> 2;
    float mu, rstd;
    q_stats(qold, outv, warp, invn, lane, mu, rstd);
    #pragma unroll
    for (int j = 0; j < 2; j++) {
        int d = ks * 64 + j * 32 + lane;
        float v = qold[warp * DD + d] + selu_f(outv[warp * DD + d] * invn);
        sx[warp][j * 32 + lane] = (v - mu) * rstd * lnw[d] + lnb[d];
    }
    if (write_q) {
        #pragma unroll 4
        for (int k = 0; k < 32; k++) {
            int d = k * 32 + lane;
            float v = qold[warp * DD + d] + selu_f(outv[warp * DD + d] * invn);
            qdst[warp * DD + d] = (v - mu) * rstd * lnw[d] + lnb[d];
        }
    }
    __syncthreads();
    colmv_compute(M, sx, Y, dt, ks);
}

// column-GEMV fused with s-reduction: X[b,k] = sum over 64 chunks of g_part.
__device__ void colmv_s(const float* __restrict__ M, float* __restrict__ Y, int cb) {
    __shared__ float sx[BB][64];
    int dt = cb & (DT - 1), ks = cb >> 2;
    #pragma unroll
    for (int p = 0; p < 2; p++) {
        int idx = p * 256 + threadIdx.x;
        int b = idx >> 6, kk = idx & 63;
        const float* pp = g_part + (size_t)(b * 64) * DD + ks * 64 + kk;
        float a0 = 0.f, a1 = 0.f, a2 = 0.f, a3 = 0.f;
        #pragma unroll 4
        for (int c = 0; c < 64; c += 4) {
            a0 += pp[(size_t)c * DD];
            a1 += pp[(size_t)(c + 1) * DD];
            a2 += pp[(size_t)(c + 2) * DD];
            a3 += pp[(size_t)(c + 3) * DD];
        }
        sx[b][kk] = (a0 + a1) + (a2 + a3);
    }
    __syncthreads();
    colmv_compute(M, sx, Y, dt, ks);
}

// row-dot matvec over all NB blocks: Y[b,r] = dot(M[r,:], X[b,:]) (+bias).
__device__ void rowdot(const float* __restrict__ M, const float* __restrict__ X,
                       float* __restrict__ Y, const float* __restrict__ bias,
                       char* smraw) {
    float4* shX = (float4*)smraw;                  // 2048 f4 = 32 KB
    const float4* Xv = (const float4*)X;
    #pragma unroll
    for (int i = threadIdx.x; i < BB * DD / 4; i += 256) shX[i] = Xv[i];
    __syncthreads();
    int warp = threadIdx.x >> 5, lane = threadIdx.x & 31;
    int row = blockIdx.x * 2 + (warp & 1);
    int b0 = (warp >> 1) * 2;
    const float4* Mr = (const float4*)(M + (size_t)row * DD);
    float a0 = 0.f, a1 = 0.f;
    #pragma unroll
    for (int j = 0; j < 8; j++) {
        float4 m = Mr[j * 32 + lane];
        float4 x0 = shX[b0 * 256 + j * 32 + lane];
        float4 x1 = shX[(b0 + 1) * 256 + j * 32 + lane];
        a0 += m.x * x0.x + m.y * x0.y + m.z * x0.z + m.w * x0.w;
        a1 += m.x * x1.x + m.y * x1.y + m.z * x1.z + m.w * x1.w;
    }
    a0 = warpSum(a0); a1 = warpSum(a1);
    if (lane == 0) {
        float bo = bias ? bias[row] : 0.f;
        Y[(size_t)b0 * DD + row] = a0 + bo;
        Y[(size_t)(b0 + 1) * DD + row] = a1 + bo;
    }
    __syncthreads();
}

// final row-dot with inline q-update: X = LN(qold + selu(outv)).
__device__ void rowdot_q(const float* __restrict__ M,
                         const float* __restrict__ qold,
                         const float* __restrict__ outv,
                         const float* __restrict__ lnw,
                         const float* __restrict__ lnb,
                         float* __restrict__ Y, const float* __restrict__ bias,
                         char* smraw) {
    float* shX = (float*)smraw;                    // [8][1024] = 32 KB
    int warp = threadIdx.x >> 5, lane = threadIdx.x & 31;
    float mu, rstd;
    q_stats(qold, outv, warp, 1.0f, lane, mu, rstd);
    #pragma unroll 4
    for (int k = 0; k < 32; k++) {
        int d = k * 32 + lane;
        float v = qold[warp * DD + d] + selu_f(outv[warp * DD + d]);
        shX[warp * DD + d] = (v - mu) * rstd * lnw[d] + lnb[d];
    }
    __syncthreads();
    int row = blockIdx.x * 2 + (warp & 1);
    int b0 = (warp >> 1) * 2;
    const float4* Mr = (const float4*)(M + (size_t)row * DD);
    const float4* x0p = (const float4*)(shX + b0 * DD);
    const float4* x1p = (const float4*)(shX + (b0 + 1) * DD);
    float a0 = 0.f, a1 = 0.f;
    #pragma unroll
    for (int j = 0; j < 8; j++) {
        float4 m = Mr[j * 32 + lane];
        float4 x0 = x0p[j * 32 + lane];
        float4 x1 = x1p[j * 32 + lane];
        a0 += m.x * x0.x + m.y * x0.y + m.z * x0.z + m.w * x0.w;
        a1 += m.x * x1.x + m.y * x1.y + m.z * x1.z + m.w * x1.w;
    }
    a0 = warpSum(a0); a1 = warpSum(a1);
    if (lane == 0) {
        float bo = bias[row];
        Y[(size_t)b0 * DD + row] = a0 + bo;
        Y[(size_t)(b0 + 1) * DD + row] = a1 + bo;
    }
}

// ---------------- big streaming pass with cp.async double buffering --------
// 512 blocks = (batch b = bid>>6, chunk = bid&63). 64 rows per block,
// 16 stages x 4 rows (16 KB contiguous), 2 smem buffers.
// Warp w: row (w>>1) of the stage, half (w&1) of the row.
#define PASS_PREFETCH(st) do {                                            \
    unsigned dstb = smbuf_u32 + (((st) & 1) ? 16384u : 0u);               \
    const float4* srcp = fb + (size_t)(st) * 1024;                        \
    _Pragma("unroll")                                                     \
    for (int j = 0; j < 4; j++) {                                         \
        unsigned da = dstb + (threadIdx.x + j * 256) * 16u;               \
        asm volatile("cp.async.cg.shared.global [%0], [%1], 16;"          \
                     :: "r"(da), "l"(srcp + threadIdx.x + j * 256));      \
    }                                                                     \
    asm volatile("cp.async.commit_group;");                               \
} while (0)

__device__ void pass_phase(const float* __restrict__ feat, int want_delta,
                           char* smraw) {
    float4* buf   = (float4*)smraw;               // [2][1024] f4 = 32 KB
    float4* sh_s  = (float4*)(smraw + 32768);     // 256 f4 = 4 KB
    float*  sh_c  = (float*)(smraw + 36864);      // 64 floats
    float*  sh_dp = (float*)(smraw + 37120);      // 16*8 floats
    unsigned smbuf_u32 = (unsigned)__cvta_generic_to_shared(buf);

    int b = blockIdx.x >> 6, chunk = blockIdx.x & 63;
    int warp = threadIdx.x >> 5, lane = threadIdx.x & 31;
    int row = warp >> 1, half = warp & 1;
    int cbase = half * 128 + lane;                // column float4 index base
    int rbase = row * 256 + cbase;                // within-stage float4 index

    if (threadIdx.x < 64) sh_c[threadIdx.x] = g_c[b * NN + chunk * 64 + threadIdx.x];
    const float4* qtv = (const float4*)(g_qt + b * DD);
    float4 q0 = qtv[cbase], q1 = qtv[cbase + 32],
           q2 = qtv[cbase + 64], q3 = qtv[cbase + 96];
    float4 s0 = make_float4(0.f, 0.f, 0.f, 0.f), s1 = s0, s2 = s0, s3 = s0;

    const float4* fb = (const float4*)feat + ((size_t)b * NN + chunk * 64) * 256;

    PASS_PREFETCH(0);
    PASS_PREFETCH(1);

    for (int s = 0; s < 16; s++) {
        if (s < 15) asm volatile("cp.async.wait_group 1;");
        else        asm volatile("cp.async.wait_group 0;");
        __syncthreads();                      // stage s ready; prev compute done
        const float4* rp = buf + ((s & 1) ? 1024 : 0) + rbase;
        float4 v0 = rp[0], v1 = rp[32], v2 = rp[64], v3 = rp[96];
        float cw = sh_c[s * 4 + row];
        if (want_delta) {
            float dp = v0.x*q0.x + v0.y*q0.y + v0.z*q0.z + v0.w*q0.w
                     + v1.x*q1.x + v1.y*q1.y + v1.z*q1.z + v1.w*q1.w
                     + v2.x*q2.x + v2.y*q2.y + v2.z*q2.z + v2.w*q2.w
                     + v3.x*q3.x + v3.y*q3.y + v3.z*q3.z + v3.w*q3.w;
            dp = warpSum(dp);
            if (lane == 0) sh_dp[s * 8 + row * 2 + half] = dp;
        }
        s0.x += cw*v0.x; s0.y += cw*v0.y; s0.z += cw*v0.z; s0.w += cw*v0.w;
        s1.x += cw*v1.x; s1.y += cw*v1.y; s1.z += cw*v1.z; s1.w += cw*v1.w;
        s2.x += cw*v2.x; s2.y += cw*v2.y; s2.z += cw*v2.z; s2.w += cw*v2.w;
        s3.x += cw*v3.x; s3.y += cw*v3.y; s3.z += cw*v3.z; s3.w += cw*v3.w;
        __syncthreads();                      // all done reading buf[s&1]
        if (s + 2 < 16) PASS_PREFETCH(s + 2);
    }

    if (want_delta && threadIdx.x < 64) {
        int st = threadIdx.x >> 2, r = threadIdx.x & 3;
        g_delta[b * NN + chunk * 64 + threadIdx.x] =
            sh_dp[st * 8 + r * 2] + sh_dp[st * 8 + r * 2 + 1];
    }
    // staggered deterministic s-reduce: 4 warps per half (rows 0..3)
    #pragma unroll
    for (int w = 0; w < 4; w++) {
        if (row == w) {
            if (w == 0) {
                sh_s[cbase] = s0; sh_s[cbase + 32] = s1;
                sh_s[cbase + 64] = s2; sh_s[cbase + 96] = s3;
            } else {
                float4 t;
                t = sh_s[cbase];      t.x+=s0.x; t.y+=s0.y; t.z+=s0.z; t.w+=s0.w; sh_s[cbase]      = t;
                t = sh_s[cbase + 32]; t.x+=s1.x; t.y+=s1.y; t.z+=s1.z; t.w+=s1.w; sh_s[cbase + 32] = t;
                t = sh_s[cbase + 64]; t.x+=s2.x; t.y+=s2.y; t.z+=s2.z; t.w+=s2.w; sh_s[cbase + 64] = t;
                t = sh_s[cbase + 96]; t.x+=s3.x; t.y+=s3.y; t.z+=s3.z; t.w+=s3.w; sh_s[cbase + 96] = t;
            }
        }
        __syncthreads();
    }
    float4* pp = (float4*)(g_part + ((size_t)b * 64 + chunk) * DD);
    pp[threadIdx.x] = sh_s[threadIdx.x];
    __syncthreads();
}

// b += standardize(delta, ddof=1), then c = softmax(b). One block per batch.
__device__ void bupd(int b) {
    __shared__ float red2[16];
    int t = threadIdx.x;
    float v[16];
    float s1 = 0.f, s2 = 0.f;
    #pragma unroll
    for (int i = 0; i < 16; i++) {
        v[i] = g_delta[b * NN + i * 256 + t];
        s1 += v[i]; s2 += v[i] * v[i];
    }
    s1 = warpSum(s1); s2 = warpSum(s2);
    if ((t & 31) == 0) { red2[t >> 5] = s1; red2[8 + (t >> 5)] = s2; }
    __syncthreads();
    s1 = 0.f; s2 = 0.f;
    #pragma unroll
    for (int w = 0; w < 8; w++) { s1 += red2[w]; s2 += red2[8 + w]; }
    float mean = s1 / (float)NN;
    float var = fmaxf((s2 - s1 * s1 / (float)NN) / (float)(NN - 1), 0.f);
    float inv = 1.0f / (sqrtf(var) + 1e-9f);
    #pragma unroll
    for (int i = 0; i < 16; i++) {
        float nb = g_b[b * NN + i * 256 + t] + (v[i] - mean) * inv;
        g_b[b * NN + i * 256 + t] = nb;
        v[i] = nb;
    }
    __syncthreads();
    softmax_store(b, v);
}

// standalone q-update for one batch: qdst = LN(qold+selu(outv*invn))
__device__ void qupd_block(int b, const float* __restrict__ qold,
                           const float* __restrict__ outv,
                           const float* __restrict__ lnw,
                           const float* __restrict__ lnb,
                           float invn, float* __restrict__ qdst) {
    __shared__ float red[16];
    int t = threadIdx.x;
    float v[4];
    float s1 = 0.f, s2 = 0.f;
    #pragma unroll
    for (int i = 0; i < 4; i++) {
        int d = i * 256 + t;
        v[i] = qold[b * DD + d] + selu_f(outv[b * DD + d] * invn);
        s1 += v[i]; s2 += v[i] * v[i];
    }
    s1 = warpSum(s1); s2 = warpSum(s2);
    if ((t & 31) == 0) { red[t >> 5] = s1; red[8 + (t >> 5)] = s2; }
    __syncthreads();
    s1 = 0.f; s2 = 0.f;
    #pragma unroll
    for (int w = 0; w < 8; w++) { s1 += red[w]; s2 += red[8 + w]; }
    float mu = s1 / (float)DD;
    float var = fmaxf(s2 / (float)DD - mu * mu, 0.f);
    float rstd = rsqrtf(var + 1e-5f);
    #pragma unroll
    for (int i = 0; i < 4; i++) {
        int d = i * 256 + t;
        qdst[b * DD + d] = (v[i] - mu) * rstd * lnw[d] + lnb[d];
    }
}

// ---------------- the one persistent megakernel ----------------
__global__ void __launch_bounds__(256, 4)
mega(const float* __restrict__ query, const float* __restrict__ feat,
     const float* __restrict__ Wh, const float* __restrict__ Wf,
     const float* __restrict__ Wg, const float* __restrict__ lnw,
     const float* __restrict__ lnb, const float* __restrict__ Wout,
     const float* __restrict__ bout, const unsigned* __restrict__ mask,
     float* __restrict__ out) {
    __shared__ __align__(16) char smraw[37888];
    unsigned sense = g_bar_sense;   // read before any block can flip it
    int bid = blockIdx.x;
    const float INVN = 1.0f / (float)NN;

    // ---- S1: Wgm = mean_g W_g ----
    {
        const float4* W = (const float4*)Wg;
        int i0 = bid * 512 + threadIdx.x;
        #pragma unroll
        for (int r = 0; r < 2; r++) {
            int i = i0 + r * 256;
            float4 a = __ldcs(W + i), b4 = __ldcs(W + i + 262144),
                   c4 = __ldcs(W + i + 524288), d4 = __ldcs(W + i + 786432);
            float4 rr;
            rr.x = 0.25f * (a.x + b4.x + c4.x + d4.x);
            rr.y = 0.25f * (a.y + b4.y + c4.y + d4.y);
            rr.z = 0.25f * (a.z + b4.z + c4.z + d4.z);
            rr.w = 0.25f * (a.w + b4.w + c4.w + d4.w);
            ((float4*)g_Wgm)[i] = rr;
        }
    }
    gbar(sense);

    // ---- S2: q0 = query @ W_h (0..63) | b from mask + softmax (64..71) ----
    if (bid < 64) {
        colmv_plain(Wh, query, g_qA, bid);
    } else if (bid < 72) {
        int b = bid - 64, t = threadIdx.x;
        float v[16];
        #pragma unroll
        for (int i = 0; i < 16; i++) {
            float bv = (mask[b * NN + i * 256 + t] != 0u) ? -1e18f : 0.0f;
            g_b[b * NN + i * 256 + t] = bv;
            v[i] = bv;
        }
        softmax_store(b, v);
    }
    gbar(sense);

    // ======== iteration 0 (q = q0 in g_qA) ========
    if (bid < 64) colmv_plain(g_Wgm, g_qA, g_tmp, bid);      // tmp = Wgm^T q0
    gbar(sense);
    rowdot(Wf, g_tmp, g_qt, nullptr, smraw);                 // qt = W_f tmp
    gbar(sense);
    pass_phase(feat, 1, smraw);                              // delta, s-partials
    gbar(sense);
    if (bid < 64) colmv_s(Wf, g_tmp2, bid);                  // tmp2 = W_f^T s
    else if (bid < 72) bupd(bid - 64);                       // b+=norm(delta); c
    gbar(sense);
    rowdot(g_Wgm, g_tmp2, g_outv, nullptr, smraw);           // outv0 = Wgm tmp2
    gbar(sense);

    // ======== iteration 1 (q1 = LN(q0+selu(outv0/n)) inline) ========
    if (bid < 64) colmv_q(g_Wgm, g_qA, g_outv, lnw, lnb, INVN,
                          (bid == 0), g_qB, g_tmp, bid);     // tmp = Wgm^T q1
    gbar(sense);
    rowdot(Wf, g_tmp, g_qt, nullptr, smraw);                 // qt = W_f tmp
    gbar(sense);
    pass_phase(feat, 1, smraw);
    gbar(sense);
    if (bid < 64) colmv_s(Wf, g_tmp2, bid);
    else if (bid < 72) bupd(bid - 64);
    gbar(sense);
    rowdot(g_Wgm, g_tmp2, g_outv, nullptr, smraw);           // outv1
    gbar(sense);

    // ======== iteration 2 (last; uses c2 from it1's bupd, no qt/delta) ========
    pass_phase(feat, 0, smraw);                              // s-partials only
    gbar(sense);
    if (bid < 64) colmv_s(Wf, g_tmp2, bid);                  // tmp2 = W_f^T s
    else if (bid < 72) qupd_block(bid - 64, g_qB, g_outv,
                                  lnw, lnb, INVN, g_qA);     // q2 -> g_qA
    gbar(sense);
    rowdot(g_Wgm, g_tmp2, g_outv, nullptr, smraw);           // outv2
    gbar(sense);
    // out = LN(q2 + selu(outv2)) @ W_out^T + b_out   (q3 inline)
    rowdot_q(Wout, g_qA, g_outv, lnw, lnb, out, bout, smraw);
}

// ---------------- host orchestration: ONE launch ----------------
extern "C" void kernel_launch(void* const* d_in, const int* in_sizes, int n_in,
                              void* d_out, int out_size) {
    const float* query = (const float*)d_in[0];
    const float* feat  = (const float*)d_in[1];
    const float* W_h   = (const float*)d_in[2];
    const float* W_f   = (const float*)d_in[3];
    const float* W_g   = (const float*)d_in[4];
    const float* ln_w  = (const float*)d_in[5];
    const float* ln_b  = (const float*)d_in[6];
    const float* W_out = (const float*)d_in[7];
    const float* b_out = (const float*)d_in[8];
    const unsigned* mask = (const unsigned*)d_in[9];
    float* out = (float*)d_out;

    mega<<<NB, 256>>>(query, feat, W_h, W_f, W_g, ln_w, ln_b, W_out, b_out,
                      mask, out);
}